// round 1
// baseline (speedup 1.0000x reference)
#include <cuda_runtime.h>

// AngularSymmetry: B=16, M=64, 6 parameter combos (lambd x zeta; ita=4 const).
// Grid: one block per (b,i) = 1024 blocks. 256 threads: t -> (j0 = t>>6, k = t&63),
// j strided by 4. Per-block smem caches the i-row quantities; d_jk/dc_jk read
// coalesced from global (L2-resident, 512KB total input).

#define B_DIM 16
#define M_DIM 64

__global__ __launch_bounds__(256, 8)
void angular_symmetry_kernel(const float* __restrict__ d_cutoff,
                             const float* __restrict__ d,
                             const float* __restrict__ coords,
                             float* __restrict__ out)
{
    const int bi = blockIdx.x;          // 0..1023
    const int b  = bi >> 6;
    const int i  = bi & 63;

    __shared__ float s_vx[M_DIM], s_vy[M_DIM], s_vz[M_DIM];
    __shared__ float s_dij[M_DIM], s_dij2[M_DIM], s_dcij[M_DIM];
    __shared__ float s_red[8][6];

    const int tid = threadIdx.x;
    const float* cb  = coords + (size_t)b * M_DIM * 3;
    const float* gd  = d        + (size_t)b * M_DIM * M_DIM;
    const float* gdc = d_cutoff + (size_t)b * M_DIM * M_DIM;

    // Fill per-i shared arrays (64 entries, threads 0..63)
    if (tid < M_DIM) {
        const int j = tid;
        float cix = cb[i * 3 + 0];
        float ciy = cb[i * 3 + 1];
        float ciz = cb[i * 3 + 2];
        s_vx[j] = cb[j * 3 + 0] - cix;
        s_vy[j] = cb[j * 3 + 1] - ciy;
        s_vz[j] = cb[j * 3 + 2] - ciz;
        float dij = gd[i * M_DIM + j];
        s_dij[j]  = dij;
        s_dij2[j] = dij * dij;
        s_dcij[j] = gdc[i * M_DIM + j];
    }
    __syncthreads();

    const int k  = tid & 63;
    const int j0 = tid >> 6;   // 0..3

    const float vkx  = s_vx[k];
    const float vky  = s_vy[k];
    const float vkz  = s_vz[k];
    const float dik  = s_dij[k];
    const float dik2 = s_dij2[k];
    const float dcik = s_dcij[k];

    float a0 = 0.f, a1 = 0.f, a2 = 0.f, a3 = 0.f, a4 = 0.f, a5 = 0.f;

    #pragma unroll 4
    for (int j = j0; j < M_DIM; j += 4) {
        float d_jk  = gd[j * M_DIM + k];
        float dc_jk = gdc[j * M_DIM + k];

        float dot = s_vx[j] * vkx + s_vy[j] * vky + s_vz[j] * vkz;
        float arg = dot / (s_dij[j] * dik + 1e-5f);
        float c   = cosf(arg);

        float ss  = s_dij2[j] + dik2 + d_jk * d_jk;
        float w   = expf(-4.0f * ss) * (s_dcij[j] * dcik * dc_jk);

        float tp  = 1.0f + c;
        float tm  = 1.0f - c;
        float tp2 = tp * tp, tp4 = tp2 * tp2, tp8 = tp4 * tp4;
        float tm2 = tm * tm, tm4 = tm2 * tm2, tm8 = tm4 * tm4;

        a0 += w * tp2;  a1 += w * tp4;  a2 += w * tp8;
        a3 += w * tm2;  a4 += w * tm4;  a5 += w * tm8;
    }

    // Warp reduce 6 accumulators
    #pragma unroll
    for (int off = 16; off > 0; off >>= 1) {
        a0 += __shfl_down_sync(0xffffffffu, a0, off);
        a1 += __shfl_down_sync(0xffffffffu, a1, off);
        a2 += __shfl_down_sync(0xffffffffu, a2, off);
        a3 += __shfl_down_sync(0xffffffffu, a3, off);
        a4 += __shfl_down_sync(0xffffffffu, a4, off);
        a5 += __shfl_down_sync(0xffffffffu, a5, off);
    }

    const int wid  = tid >> 5;   // 0..7
    const int lane = tid & 31;
    if (lane == 0) {
        s_red[wid][0] = a0; s_red[wid][1] = a1; s_red[wid][2] = a2;
        s_red[wid][3] = a3; s_red[wid][4] = a4; s_red[wid][5] = a5;
    }
    __syncthreads();

    if (tid < 6) {
        float s = 0.f;
        #pragma unroll
        for (int w = 0; w < 8; w++) s += s_red[w][tid];
        // scale = 2^(1 - zeta), zeta = [2,4,8,2,4,8]
        const float scale = (tid % 3 == 0) ? 0.5f : ((tid % 3 == 1) ? 0.125f : 0.0078125f);
        out[(size_t)bi * 6 + tid] = s * scale;
    }
}

extern "C" void kernel_launch(void* const* d_in, const int* in_sizes, int n_in,
                              void* d_out, int out_size)
{
    const float* d_cutoff = (const float*)d_in[0];
    const float* d        = (const float*)d_in[1];
    const float* coords   = (const float*)d_in[2];
    float* out = (float*)d_out;

    angular_symmetry_kernel<<<B_DIM * M_DIM, 256>>>(d_cutoff, d, coords, out);
}

// round 2
// speedup vs baseline: 1.3361x; 1.3361x over previous
#include <cuda_runtime.h>

// AngularSymmetry: B=16, M=64, 6 param combos (lambda in {+1,-1} x zeta in {2,4,8}; ita=4).
// One block per (b,i). Unordered-pair enumeration via cyclic distance m (1..32):
//   - each unordered pair {j,k} computed once; both ordered terms recovered via
//     g[j,k] + g[k,j] where g[p] = __expf(-4*d[p]^2) * dc[p] (precomputed 16KB tile)
//   - weight: 1 for m in 1..31, 0.5 for m=32 (double-covered), 0.125 for the
//     diagonal (covered by all 4 thread-groups)
//   - w = F[j]*F[k]*(g_jk + g_kj),  F[j] = dc_ij * __expf(-4*d_ij^2)
// Inner loop keeps div.rn + accurate cosf (must match JAX bitwise-ish: cos args
// reach ~1e6 when d_ij*d_ik ~ 1e-5, so theta must be IEEE-identical).

#define B_DIM 16
#define M_DIM 64

__global__ __launch_bounds__(256, 7)
void angular_symmetry_kernel(const float* __restrict__ d_cutoff,
                             const float* __restrict__ d,
                             const float* __restrict__ coords,
                             float* __restrict__ out)
{
    const int bi = blockIdx.x;          // 0..1023
    const int b  = bi >> 6;
    const int i  = bi & 63;

    __shared__ float4 s_v4[M_DIM];          // {vx, vy, vz, d_ij}
    __shared__ float  s_F[M_DIM];           // dc_ij * exp(-4 d_ij^2)
    __shared__ float  s_g[M_DIM * M_DIM];   // exp(-4 d_jk^2) * dc_jk   (16 KB)
    __shared__ float  s_red[8][6];

    const int tid = threadIdx.x;
    const float* gd  = d        + (size_t)b * M_DIM * M_DIM;
    const float* gdc = d_cutoff + (size_t)b * M_DIM * M_DIM;
    const float* cb  = coords   + (size_t)b * M_DIM * 3;

    // ---- Preload tile: g[p] = __expf(-4*d[p]^2) * dc[p], coalesced float4 ----
    {
        const float4* gd4  = (const float4*)gd;
        const float4* gdc4 = (const float4*)gdc;
        float4* sg4 = (float4*)s_g;
        #pragma unroll
        for (int c = 0; c < 4; c++) {
            int p = tid + c * 256;          // float4 index 0..1023
            float4 dv = gd4[p];
            float4 cv = gdc4[p];
            float4 gv;
            gv.x = __expf(-4.0f * dv.x * dv.x) * cv.x;
            gv.y = __expf(-4.0f * dv.y * dv.y) * cv.y;
            gv.z = __expf(-4.0f * dv.z * dv.z) * cv.z;
            gv.w = __expf(-4.0f * dv.w * dv.w) * cv.w;
            sg4[p] = gv;
        }
    }

    // ---- i-row quantities (threads 0..63) ----
    if (tid < M_DIM) {
        const int j = tid;
        float cix = cb[i * 3 + 0];
        float ciy = cb[i * 3 + 1];
        float ciz = cb[i * 3 + 2];
        float4 v;
        v.x = cb[j * 3 + 0] - cix;
        v.y = cb[j * 3 + 1] - ciy;
        v.z = cb[j * 3 + 2] - ciz;
        float dij = gd[i * M_DIM + j];
        v.w = dij;
        s_v4[j] = v;
        s_F[j]  = gdc[i * M_DIM + j] * __expf(-4.0f * dij * dij);
    }
    __syncthreads();

    const int k = tid & 63;
    const int g = tid >> 6;     // 0..3

    const float4 vk = s_v4[k];
    const float  Fk = s_F[k];

    float a0 = 0.f, a1 = 0.f, a2 = 0.f, a3 = 0.f, a4 = 0.f, a5 = 0.f;

    // m = 4t + g + 1 for t=0..7  (covers m = 1..32 across 4 groups)
    #pragma unroll 4
    for (int t = 0; t < 8; t++) {
        const int   m   = 4 * t + g + 1;
        const float wgt = (m == 32) ? 0.5f : 1.0f;
        const int   j   = (k + m) & 63;

        float4 vj  = s_v4[j];
        float  Fj  = s_F[j];
        float  gjk = s_g[(j << 6) + k];
        float  gkj = s_g[(k << 6) + j];

        float dot = vj.x * vk.x + vj.y * vk.y + vj.z * vk.z;
        float den = vj.w * vk.w + 1e-5f;
        float c   = cosf(dot / den);          // div.rn + accurate cosf (match JAX)

        float w = wgt * Fj * Fk * (gjk + gkj);

        float tp = 1.0f + c, tm = 1.0f - c;
        float tp2 = tp * tp, tp4 = tp2 * tp2, tp8 = tp4 * tp4;
        float tm2 = tm * tm, tm4 = tm2 * tm2, tm8 = tm4 * tm4;

        a0 += w * tp2;  a1 += w * tp4;  a2 += w * tp8;
        a3 += w * tm2;  a4 += w * tm4;  a5 += w * tm8;
    }

    // Diagonal term j == k, done by all 4 groups -> weight 1/4; generic body
    // computes (g_kk + g_kk) = 2*g_kk, so weight 0.125 total.
    {
        float gkk = s_g[(k << 6) + k];
        float dot = vk.x * vk.x + vk.y * vk.y + vk.z * vk.z;
        float den = vk.w * vk.w + 1e-5f;
        float c   = cosf(dot / den);

        float w = 0.125f * Fk * Fk * (gkk + gkk);

        float tp = 1.0f + c, tm = 1.0f - c;
        float tp2 = tp * tp, tp4 = tp2 * tp2, tp8 = tp4 * tp4;
        float tm2 = tm * tm, tm4 = tm2 * tm2, tm8 = tm4 * tm4;

        a0 += w * tp2;  a1 += w * tp4;  a2 += w * tp8;
        a3 += w * tm2;  a4 += w * tm4;  a5 += w * tm8;
    }

    // ---- Reduce 6 accumulators: warp shuffle, then cross-warp via smem ----
    #pragma unroll
    for (int off = 16; off > 0; off >>= 1) {
        a0 += __shfl_down_sync(0xffffffffu, a0, off);
        a1 += __shfl_down_sync(0xffffffffu, a1, off);
        a2 += __shfl_down_sync(0xffffffffu, a2, off);
        a3 += __shfl_down_sync(0xffffffffu, a3, off);
        a4 += __shfl_down_sync(0xffffffffu, a4, off);
        a5 += __shfl_down_sync(0xffffffffu, a5, off);
    }

    const int wid  = tid >> 5;
    const int lane = tid & 31;
    if (lane == 0) {
        s_red[wid][0] = a0; s_red[wid][1] = a1; s_red[wid][2] = a2;
        s_red[wid][3] = a3; s_red[wid][4] = a4; s_red[wid][5] = a5;
    }
    __syncthreads();

    if (tid < 6) {
        float s = 0.f;
        #pragma unroll
        for (int w = 0; w < 8; w++) s += s_red[w][tid];
        // scale = 2^(1 - zeta), zeta order = [2,4,8,2,4,8]
        const float scale = (tid % 3 == 0) ? 0.5f : ((tid % 3 == 1) ? 0.125f : 0.0078125f);
        out[(size_t)bi * 6 + tid] = s * scale;
    }
}

extern "C" void kernel_launch(void* const* d_in, const int* in_sizes, int n_in,
                              void* d_out, int out_size)
{
    const float* d_cutoff = (const float*)d_in[0];
    const float* d        = (const float*)d_in[1];
    const float* coords   = (const float*)d_in[2];
    float* out = (float*)d_out;

    angular_symmetry_kernel<<<B_DIM * M_DIM, 256>>>(d_cutoff, d, coords, out);
}

// round 4
// speedup vs baseline: 1.6794x; 1.2569x over previous
#include <cuda_runtime.h>

// AngularSymmetry B=16, M=64. Two kernels:
//  prep: G[b,j,k] = __expf(-4 d^2)*dc ; S[b,j,k] = wgt*(g_jk + g_kj)
//        wgt = 0.125 (j==k, counted by all 4 groups, pair-form doubles it),
//              0.5 (cyclic dist 32, enumerated from both endpoints),
//              1 otherwise
//  main: one block per (b,i); unordered pairs via cyclic distance m=1..32
//        (+diagonal), 6-instr Cody-Waite cos, packed f32x2 powers/accums,
//        Fk hoisted out of the loop.

#define B_DIM 16
#define M_DIM 64

__device__ float G_buf[B_DIM * M_DIM * M_DIM];
__device__ float S_buf[B_DIM * M_DIM * M_DIM];

__global__ void prep_kernel(const float* __restrict__ d,
                            const float* __restrict__ dc)
{
    const int e = blockIdx.x * 256 + threadIdx.x;  // 0..65535
    const int b = e >> 12;
    const int j = (e >> 6) & 63;
    const int k = e & 63;
    const float* db  = d  + b * 4096;
    const float* dcb = dc + b * 4096;

    float djk = db[j * 64 + k];
    float dkj = db[k * 64 + j];
    float gjk = __expf(-4.0f * djk * djk) * dcb[j * 64 + k];
    float gkj = __expf(-4.0f * dkj * dkj) * dcb[k * 64 + j];

    G_buf[e] = gjk;

    const int dd = (j - k) & 63;
    const float wgt = (dd == 0) ? 0.125f : ((dd == 32) ? 0.5f : 1.0f);
    S_buf[e] = wgt * (gjk + gkj);
}

// ---- packed f32x2 helpers ----
__device__ __forceinline__ unsigned long long pack2(float lo, float hi) {
    unsigned long long r;
    asm("mov.b64 %0, {%1, %2};" : "=l"(r) : "f"(lo), "f"(hi));
    return r;
}
__device__ __forceinline__ void unpack2(unsigned long long v, float& lo, float& hi) {
    asm("mov.b64 {%0, %1}, %2;" : "=f"(lo), "=f"(hi) : "l"(v));
}
__device__ __forceinline__ unsigned long long mul2(unsigned long long a, unsigned long long b) {
    unsigned long long r;
    asm("mul.rn.f32x2 %0, %1, %2;" : "=l"(r) : "l"(a), "l"(b));
    return r;
}
__device__ __forceinline__ unsigned long long add2(unsigned long long a, unsigned long long b) {
    unsigned long long r;
    asm("add.rn.f32x2 %0, %1, %2;" : "=l"(r) : "l"(a), "l"(b));
    return r;
}
__device__ __forceinline__ unsigned long long fma2(unsigned long long a, unsigned long long b,
                                                   unsigned long long c) {
    unsigned long long r;
    asm("fma.rn.f32x2 %0, %1, %2, %3;" : "=l"(r) : "l"(a), "l"(b), "l"(c));
    return r;
}

// Fast cos: exact RNE(x/2pi) via magic-number fma, 2-word Cody-Waite
// reduction, MUFU cos on reduced arg. Phase error ~5e-7 rad up to |x|~4e6.
__device__ __forceinline__ float fast_cos(float x) {
    const float MAGIC = 12582912.0f;                 // 1.5 * 2^23
    float q = fmaf(x, 0.15915494309189535f, MAGIC) - MAGIC;
    float r = fmaf(q, -6.28318548202514648f, x);     // C1 = fp32(2*pi)
    r = fmaf(q, 1.74845553146599e-7f, r);            // C2 correction
    return __cosf(r);
}

__global__ __launch_bounds__(256, 7)
void angular_main(const float* __restrict__ d,
                  const float* __restrict__ coords,
                  float* __restrict__ out)
{
    const int bi = blockIdx.x;      // 0..1023
    const int b  = bi >> 6;
    const int i  = bi & 63;

    __shared__ float4 s_v4[M_DIM];              // {vx, vy, vz, d_ij}
    __shared__ float  s_F[M_DIM];               // G[b][i][j]
    __shared__ float  s_S[M_DIM * M_DIM];       // 16 KB
    __shared__ float  s_red[8][6];

    const int tid = threadIdx.x;
    const float* cb = coords + (size_t)b * M_DIM * 3;

    // Preload S tile (coalesced float4, no math)
    {
        float4* sS4 = (float4*)s_S;
        const float4* gS4 = (const float4*)(S_buf + b * 4096);
        #pragma unroll
        for (int c = 0; c < 4; c++) {
            int p = tid + c * 256;
            sS4[p] = gS4[p];
        }
    }

    if (tid < M_DIM) {
        const int j = tid;
        float cix = cb[i * 3 + 0];
        float ciy = cb[i * 3 + 1];
        float ciz = cb[i * 3 + 2];
        float4 v;
        v.x = cb[j * 3 + 0] - cix;
        v.y = cb[j * 3 + 1] - ciy;
        v.z = cb[j * 3 + 2] - ciz;
        v.w = d[(size_t)b * 4096 + i * 64 + j];
        s_v4[j] = v;
        s_F[j]  = G_buf[b * 4096 + i * 64 + j];
    }
    __syncthreads();

    const int k = tid & 63;
    const int g = tid >> 6;    // 0..3

    const float4 vk = s_v4[k];
    const float  Fk = s_F[k];

    const unsigned long long ONE2 = 0x3F8000003F800000ull;  // (1.0f, 1.0f)
    unsigned long long acc2 = 0ull, acc4 = 0ull, acc8 = 0ull;

    // t = 0..7: m = 4t+g+1 (covers m=1..32 across groups); t = 8: diagonal
    #pragma unroll
    for (int t = 0; t < 9; t++) {
        const int j = (t < 8) ? ((k + 4 * t + g + 1) & 63) : k;

        float4 vj = s_v4[j];
        float  Fj = s_F[j];
        float  Sv = s_S[(j << 6) + k];

        float dot = vj.x * vk.x + vj.y * vk.y + vj.z * vk.z;
        float den = vj.w * vk.w + 1e-5f;
        float c   = fast_cos(dot / den);      // IEEE div kept for tail accuracy
        float w   = Fj * Sv;                  // Fk applied after the loop

        unsigned long long cc  = pack2(c, __int_as_float(__float_as_int(c) ^ 0x80000000));
        unsigned long long tpm = add2(cc, ONE2);        // (1+c, 1-c)
        unsigned long long t2  = mul2(tpm, tpm);
        unsigned long long t4  = mul2(t2, t2);
        unsigned long long t8  = mul2(t4, t4);
        unsigned long long wp  = pack2(w, w);

        acc2 = fma2(t2, wp, acc2);
        acc4 = fma2(t4, wp, acc4);
        acc8 = fma2(t8, wp, acc8);
    }

    // Apply hoisted Fk (packed)
    {
        unsigned long long Fkp = pack2(Fk, Fk);
        acc2 = mul2(acc2, Fkp);
        acc4 = mul2(acc4, Fkp);
        acc8 = mul2(acc8, Fkp);
    }

    float a0, a1, a2, a3, a4, a5;
    unpack2(acc2, a0, a3);
    unpack2(acc4, a1, a4);
    unpack2(acc8, a2, a5);

    #pragma unroll
    for (int off = 16; off > 0; off >>= 1) {
        a0 += __shfl_down_sync(0xffffffffu, a0, off);
        a1 += __shfl_down_sync(0xffffffffu, a1, off);
        a2 += __shfl_down_sync(0xffffffffu, a2, off);
        a3 += __shfl_down_sync(0xffffffffu, a3, off);
        a4 += __shfl_down_sync(0xffffffffu, a4, off);
        a5 += __shfl_down_sync(0xffffffffu, a5, off);
    }

    const int wid  = tid >> 5;
    const int lane = tid & 31;
    if (lane == 0) {
        s_red[wid][0] = a0; s_red[wid][1] = a1; s_red[wid][2] = a2;
        s_red[wid][3] = a3; s_red[wid][4] = a4; s_red[wid][5] = a5;
    }
    __syncthreads();

    if (tid < 6) {
        float s = 0.f;
        #pragma unroll
        for (int w = 0; w < 8; w++) s += s_red[w][tid];
        // scale = 2^(1 - zeta), zeta order = [2,4,8,2,4,8]
        const float scale = (tid % 3 == 0) ? 0.5f : ((tid % 3 == 1) ? 0.125f : 0.0078125f);
        out[(size_t)bi * 6 + tid] = s * scale;
    }
}

extern "C" void kernel_launch(void* const* d_in, const int* in_sizes, int n_in,
                              void* d_out, int out_size)
{
    const float* d_cutoff = (const float*)d_in[0];
    const float* d        = (const float*)d_in[1];
    const float* coords   = (const float*)d_in[2];
    float* out = (float*)d_out;

    prep_kernel<<<256, 256>>>(d, d_cutoff);
    angular_main<<<B_DIM * M_DIM, 256>>>(d, coords, out);
}

// round 5
// speedup vs baseline: 1.7084x; 1.0173x over previous
#include <cuda_runtime.h>

// AngularSymmetry B=16, M=64.
//  prep (grid 16, one block per batch): smem-transposed, fully coalesced
//    S[b,j,k] = wgt * (g_jk + g_kj),  g = __expf(-4 d^2) * dc
//    wgt = 0.125 (diag), 0.5 (cyclic dist 32), 1 otherwise
//  main (grid 512, one block per (b, i-pair)): unordered pairs via cyclic
//    distance m=1..32 (+diagonal); two independent i-chains per thread for
//    ILP; Cody-Waite fast cos; packed f32x2 powers/accumulators/reduction.

#define B_DIM 16
#define M_DIM 64

__device__ float S_buf[B_DIM * M_DIM * M_DIM];

__global__ __launch_bounds__(256)
void prep_kernel(const float* __restrict__ d, const float* __restrict__ dc)
{
    __shared__ float sg[M_DIM * 65];          // stride-65: conflict-free transpose
    const int b   = blockIdx.x;
    const int tid = threadIdx.x;
    const float* db  = d  + b * 4096;
    const float* dcb = dc + b * 4096;

    #pragma unroll
    for (int c = 0; c < 16; c++) {
        int e = tid + c * 256;
        int j = e >> 6, k = e & 63;
        float dv = db[e];
        sg[j * 65 + k] = __expf(-4.0f * dv * dv) * dcb[e];
    }
    __syncthreads();

    #pragma unroll
    for (int c = 0; c < 16; c++) {
        int e = tid + c * 256;
        int j = e >> 6, k = e & 63;
        int dd = (j - k) & 63;
        float w = (dd == 0) ? 0.125f : ((dd == 32) ? 0.5f : 1.0f);
        S_buf[b * 4096 + e] = w * (sg[j * 65 + k] + sg[k * 65 + j]);
    }
}

// ---- packed f32x2 helpers ----
typedef unsigned long long u64;
__device__ __forceinline__ u64 pack2(float lo, float hi) {
    u64 r; asm("mov.b64 %0, {%1, %2};" : "=l"(r) : "f"(lo), "f"(hi)); return r;
}
__device__ __forceinline__ void unpack2(u64 v, float& lo, float& hi) {
    asm("mov.b64 {%0, %1}, %2;" : "=f"(lo), "=f"(hi) : "l"(v));
}
__device__ __forceinline__ u64 mul2(u64 a, u64 b) {
    u64 r; asm("mul.rn.f32x2 %0, %1, %2;" : "=l"(r) : "l"(a), "l"(b)); return r;
}
__device__ __forceinline__ u64 add2(u64 a, u64 b) {
    u64 r; asm("add.rn.f32x2 %0, %1, %2;" : "=l"(r) : "l"(a), "l"(b)); return r;
}
__device__ __forceinline__ u64 fma2(u64 a, u64 b, u64 c) {
    u64 r; asm("fma.rn.f32x2 %0, %1, %2, %3;" : "=l"(r) : "l"(a), "l"(b), "l"(c)); return r;
}

// Fast cos: exact RNE(x/2pi) via magic-number fma, 2-word Cody-Waite
// reduction, MUFU cos. Phase error ~5e-7 rad up to |x|~4e6.
__device__ __forceinline__ float fast_cos(float x) {
    const float MAGIC = 12582912.0f;                 // 1.5 * 2^23
    float q = fmaf(x, 0.15915494309189535f, MAGIC) - MAGIC;
    float r = fmaf(q, -6.28318548202514648f, x);     // C1 = fp32(2*pi)
    r = fmaf(q, 1.74845553146599e-7f, r);            // C2 correction
    return __cosf(r);
}

__global__ __launch_bounds__(256, 4)
void angular_main(const float* __restrict__ dc,
                  const float* __restrict__ d,
                  const float* __restrict__ coords,
                  float* __restrict__ out)
{
    const int blk = blockIdx.x;        // 0..511
    const int b   = blk >> 5;
    const int i0  = (blk & 31) << 1;
    const int i1  = i0 + 1;

    __shared__ float4 s_va[M_DIM], s_vb[M_DIM];   // {vx, vy, vz, d_ij}
    __shared__ float  s_Fa[M_DIM], s_Fb[M_DIM];   // dc_ij * exp(-4 d_ij^2)
    __shared__ float  s_S[M_DIM * M_DIM];         // 16 KB
    __shared__ u64    s_red[8][6];

    const int tid = threadIdx.x;

    // Preload S tile (coalesced float4, no math)
    {
        float4* sS4 = (float4*)s_S;
        const float4* gS4 = (const float4*)(S_buf + b * 4096);
        #pragma unroll
        for (int c = 0; c < 4; c++) {
            int p = tid + c * 256;
            sS4[p] = gS4[p];
        }
    }

    // i-row quantities for both i's (threads 0..127)
    if (tid < 128) {
        const int ii = (tid < 64) ? i0 : i1;
        const int j  = tid & 63;
        const float* cb = coords + (size_t)b * 192;
        float cx = cb[ii * 3 + 0];
        float cy = cb[ii * 3 + 1];
        float cz = cb[ii * 3 + 2];
        float4 v;
        v.x = cb[j * 3 + 0] - cx;
        v.y = cb[j * 3 + 1] - cy;
        v.z = cb[j * 3 + 2] - cz;
        v.w = d[(size_t)b * 4096 + ii * 64 + j];
        float F = dc[(size_t)b * 4096 + ii * 64 + j] * __expf(-4.0f * v.w * v.w);
        if (tid < 64) { s_va[j] = v; s_Fa[j] = F; }
        else          { s_vb[j] = v; s_Fb[j] = F; }
    }
    __syncthreads();

    const int k = tid & 63;
    const int g = tid >> 6;    // 0..3

    const float4 vka = s_va[k];
    const float4 vkb = s_vb[k];
    const float  Fka = s_Fa[k];
    const float  Fkb = s_Fb[k];

    const u64 ONE2 = 0x3F8000003F800000ull;  // (1.0f, 1.0f)
    u64 A2 = 0, A4 = 0, A8 = 0;              // i0: (lambda=+1, lambda=-1)
    u64 B2 = 0, B4 = 0, B8 = 0;              // i1

    // t = 0..7: m = 4t+g+1 (covers m=1..32 across groups); t = 8: diagonal
    #pragma unroll
    for (int t = 0; t < 9; t++) {
        const int j = (t < 8) ? ((k + 4 * t + g + 1) & 63) : k;

        const float Sv = s_S[(j << 6) + k];          // shared by both i's

        // ---- chain A (i0) ----
        float4 vja = s_va[j];
        float  Fja = s_Fa[j];
        float dotA = vja.x * vka.x + vja.y * vka.y + vja.z * vka.z;
        float denA = vja.w * vka.w + 1e-5f;
        float cA   = fast_cos(dotA / denA);
        float wA   = Fja * Sv;

        // ---- chain B (i1) ----
        float4 vjb = s_vb[j];
        float  Fjb = s_Fb[j];
        float dotB = vjb.x * vkb.x + vjb.y * vkb.y + vjb.z * vkb.z;
        float denB = vjb.w * vkb.w + 1e-5f;
        float cB   = fast_cos(dotB / denB);
        float wB   = Fjb * Sv;

        u64 ccA  = pack2(cA, __int_as_float(__float_as_int(cA) ^ 0x80000000));
        u64 tpmA = add2(ccA, ONE2);
        u64 t2A  = mul2(tpmA, tpmA);
        u64 t4A  = mul2(t2A, t2A);
        u64 t8A  = mul2(t4A, t4A);
        u64 wpA  = pack2(wA, wA);
        A2 = fma2(t2A, wpA, A2);
        A4 = fma2(t4A, wpA, A4);
        A8 = fma2(t8A, wpA, A8);

        u64 ccB  = pack2(cB, __int_as_float(__float_as_int(cB) ^ 0x80000000));
        u64 tpmB = add2(ccB, ONE2);
        u64 t2B  = mul2(tpmB, tpmB);
        u64 t4B  = mul2(t2B, t2B);
        u64 t8B  = mul2(t4B, t4B);
        u64 wpB  = pack2(wB, wB);
        B2 = fma2(t2B, wpB, B2);
        B4 = fma2(t4B, wpB, B4);
        B8 = fma2(t8B, wpB, B8);
    }

    // Apply hoisted Fk (packed) — must happen before reduction (Fk varies by k)
    {
        u64 Fpa = pack2(Fka, Fka);
        u64 Fpb = pack2(Fkb, Fkb);
        A2 = mul2(A2, Fpa); A4 = mul2(A4, Fpa); A8 = mul2(A8, Fpa);
        B2 = mul2(B2, Fpb); B4 = mul2(B4, Fpb); B8 = mul2(B8, Fpb);
    }

    // Packed warp reduction (64-bit shuffles + add.rn.f32x2)
    #pragma unroll
    for (int off = 16; off > 0; off >>= 1) {
        A2 = add2(A2, __shfl_down_sync(0xffffffffu, A2, off));
        A4 = add2(A4, __shfl_down_sync(0xffffffffu, A4, off));
        A8 = add2(A8, __shfl_down_sync(0xffffffffu, A8, off));
        B2 = add2(B2, __shfl_down_sync(0xffffffffu, B2, off));
        B4 = add2(B4, __shfl_down_sync(0xffffffffu, B4, off));
        B8 = add2(B8, __shfl_down_sync(0xffffffffu, B8, off));
    }

    const int wid  = tid >> 5;
    const int lane = tid & 31;
    if (lane == 0) {
        s_red[wid][0] = A2; s_red[wid][1] = A4; s_red[wid][2] = A8;
        s_red[wid][3] = B2; s_red[wid][4] = B4; s_red[wid][5] = B8;
    }
    __syncthreads();

    if (tid < 6) {
        u64 s = s_red[0][tid];
        #pragma unroll
        for (int w = 1; w < 8; w++) s = add2(s, s_red[w][tid]);
        float plus, minus;
        unpack2(s, plus, minus);
        const int ii = (tid < 3) ? i0 : i1;
        const int z  = (tid < 3) ? tid : tid - 3;     // zeta index 0..2
        const float scale = (z == 0) ? 0.5f : ((z == 1) ? 0.125f : 0.0078125f);
        float* o = out + ((size_t)b * 64 + ii) * 6;
        o[z]     = plus  * scale;     // lambda = +1
        o[3 + z] = minus * scale;     // lambda = -1
    }
}

extern "C" void kernel_launch(void* const* d_in, const int* in_sizes, int n_in,
                              void* d_out, int out_size)
{
    const float* d_cutoff = (const float*)d_in[0];
    const float* d        = (const float*)d_in[1];
    const float* coords   = (const float*)d_in[2];
    float* out = (float*)d_out;

    prep_kernel<<<B_DIM, 256>>>(d, d_cutoff);
    angular_main<<<512, 256>>>(d_cutoff, d, coords, out);
}